// round 13
// baseline (speedup 1.0000x reference)
#include <cuda_runtime.h>
#include <cuda_fp16.h>
#include <cstdint>

#define Bb 4
#define Ss 2048
#define Dd 1024

#define BM 128
#define BN 128
#define BK 64                                  // fp16: 64 * 2B = 128B per row
#define A_BYTES (BM * 128)                     // 16KB
#define STAGE_BYTES (2 * A_BYTES)              // 32KB
#define SMEM_BYTES (2 * STAGE_BYTES)           // 64KB, 2 stages -> 3 CTAs/SM
#define NT 128                                 // threads per GEMM CTA (4 warps, 2x2)

// ---------------- device scratch (allocation-free rule) ----------------
__device__ __align__(1024) __half g_x16[Bb * Ss * Dd];
__device__ __align__(1024) __half g_W16[3 * Dd * Dd];
__device__ __align__(1024) __half g_Q16[Bb * Ss * Dd];
__device__ __align__(1024) __half g_K16[Bb * Ss * Dd];
__device__ __align__(1024) __half g_Vt16[Bb * Ss * Dd];
__device__ __align__(1024) __half g_P16[Bb * Ss * Ss];
__device__ float g_rowsum[Bb * Ss];

// ---------------- helpers ----------------
__device__ __forceinline__ uint32_t smem_u32(const void* p) {
    uint32_t a;
    asm("{ .reg .u64 t; cvta.to.shared.u64 t, %1; cvt.u32.u64 %0, t; }" : "=r"(a) : "l"(p));
    return a;
}
__device__ __forceinline__ void cp16(uint32_t dst, const void* src) {
    asm volatile("cp.async.cg.shared.global [%0], [%1], 16;" :: "r"(dst), "l"(src));
}
__device__ __forceinline__ void cp_commit() {
    asm volatile("cp.async.commit_group;" ::: "memory");
}
__device__ __forceinline__ void cp_wait1() {
    asm volatile("cp.async.wait_group 1;" ::: "memory");
}
__device__ __forceinline__ void ldsm4(uint32_t& r0, uint32_t& r1, uint32_t& r2, uint32_t& r3,
                                      uint32_t addr) {
    asm volatile("ldmatrix.sync.aligned.m8n8.x4.shared.b16 {%0,%1,%2,%3}, [%4];"
                 : "=r"(r0), "=r"(r1), "=r"(r2), "=r"(r3) : "r"(addr));
}
__device__ __forceinline__ void mma_f16(float* c, const uint32_t* a, uint32_t b0, uint32_t b1) {
    asm volatile(
        "mma.sync.aligned.m16n8k16.row.col.f32.f16.f16.f32 "
        "{%0,%1,%2,%3}, {%4,%5,%6,%7}, {%8,%9}, {%0,%1,%2,%3};"
        : "+f"(c[0]), "+f"(c[1]), "+f"(c[2]), "+f"(c[3])
        : "r"(a[0]), "r"(a[1]), "r"(a[2]), "r"(a[3]), "r"(b0), "r"(b1));
}

// ======= fp16 mma.sync GEMM body: 128 threads, 4 warps 2(M)x2(N), warp tile 64x64 =======
// 2-stage smem ring (64KB) -> 3 CTAs/SM = 12 warps (was 8). R11/12 ncu showed
// tensor=52%, issue=30%, occ=11%: warps stall ~half the time and 2 warps/SMSP
// can't cover it; a third warp per scheduler is the remaining lever. 2 stages
// force load-after-compute (second barrier per iter), cheap vs the coverage.
// launch_bounds(128,3) caps regs at 170; core demand 160 (128 acc + 32 frags).
// EPI: 1 = fp16 out, alpha + per-column bias
//      2 = fp16 out, alpha + per-row bias
//      3 = fp16 out, exp(alpha*s)*2^-4, fused row-sum atomicAdd into aux
//      4 = fp32 out, acc * (1/aux[row])          (PV normalize)
template <int EPI>
__device__ __forceinline__ void gemm_body(
    const __half* __restrict__ Ab, const __half* __restrict__ Bg0,
    const float* __restrict__ bias, float* __restrict__ aux,
    void* __restrict__ Cv, int Ntot, int Ktot, float alpha,
    int rowBase, int colBase, uint32_t sb)
{
    const int tid = threadIdx.x;
    const int lane = tid & 31;
    const int wid = tid >> 5;
    const int wm = wid & 1;        // 2 warps in M (64 rows each)
    const int wn = wid >> 1;       // 2 warps in N (64 cols each)

    // -------- loader precompute: 128 threads, 16 rows per pass, 8 passes/operand --------
    const int lr = tid >> 3;       // 0..15
    const int lc = tid & 7;        // 0..7
    const uint32_t soff0 = lr * 128 + ((uint32_t)(lc ^ (lr & 7)) << 4);
    const int st16 = 16 * Ktot;    // element stride between passes
    const __half* pA = Ab + (long long)lr * Ktot + lc * 8;
    const __half* pB = Bg0 + (long long)lr * Ktot + lc * 8;

    const int frow = lane & 15;
    const int fkc = lane >> 4;

    float acc[4][8][4];
#pragma unroll
    for (int i = 0; i < 4; i++)
#pragma unroll
        for (int j = 0; j < 8; j++)
#pragma unroll
            for (int q = 0; q < 4; q++) acc[i][j][q] = 0.0f;

    const int kIters = Ktot / BK;

    auto load_stage = [&](int buf) {
        const uint32_t sbase = sb + buf * STAGE_BYTES + soff0;
#pragma unroll
        for (int p = 0; p < 8; p++) {
            cp16(sbase + p * 2048, pA + p * st16);
            cp16(sbase + A_BYTES + p * 2048, pB + p * st16);
        }
        pA += BK;
        pB += BK;
    };

    load_stage(0); cp_commit();
    load_stage(1); cp_commit();

    int arow[4], brow[4];
#pragma unroll
    for (int mt = 0; mt < 4; mt++) arow[mt] = wm * 64 + mt * 16 + frow;
#pragma unroll
    for (int p = 0; p < 4; p++) brow[p] = wn * 64 + p * 16 + frow;

    for (int it = 0; it < kIters; it++) {
        cp_wait1();                 // stage it landed (at most stage it+1 in flight)
        __syncthreads();

        const uint32_t As = sb + (it & 1) * STAGE_BYTES;
        const uint32_t Bs = As + A_BYTES;

#pragma unroll
        for (int ks = 0; ks < 4; ks++) {            // 4 x k16 steps = K64
            const int chunk = 2 * ks + fkc;
            uint32_t a[4][4];
#pragma unroll
            for (int mt = 0; mt < 4; mt++) {
                const uint32_t ad = As + arow[mt] * 128 +
                                    ((uint32_t)(chunk ^ (arow[mt] & 7)) << 4);
                ldsm4(a[mt][0], a[mt][1], a[mt][2], a[mt][3], ad);
            }
            uint32_t b[4][4];
#pragma unroll
            for (int p = 0; p < 4; p++) {
                const uint32_t bd = Bs + brow[p] * 128 +
                                    ((uint32_t)(chunk ^ (brow[p] & 7)) << 4);
                ldsm4(b[p][0], b[p][1], b[p][2], b[p][3], bd);
            }
#pragma unroll
            for (int mt = 0; mt < 4; mt++)
#pragma unroll
                for (int nt = 0; nt < 8; nt++) {
                    const int p = nt >> 1, o = nt & 1;
                    mma_f16(acc[mt][nt], a[mt], b[p][o], b[p][2 + o]);
                }
        }

        // all warps done reading s[it&1]; refill it with chunk it+2
        __syncthreads();
        if (it + 2 < kIters) load_stage(it & 1);
        cp_commit();
    }

    // ---- epilogue ----
    const int g = lane >> 2;
    const int cpair = (lane & 3) * 2;
#pragma unroll
    for (int mt = 0; mt < 4; mt++) {
        const long long r0 = rowBase + wm * 64 + mt * 16 + g;
        const long long r1 = r0 + 8;
        float rb0 = 0.f, rb1 = 0.f;
        if (EPI == 2) { rb0 = bias[r0]; rb1 = bias[r1]; }
        if (EPI == 4) { rb0 = 1.0f / aux[r0]; rb1 = 1.0f / aux[r1]; }
        float sum0 = 0.f, sum1 = 0.f;
#pragma unroll
        for (int nt = 0; nt < 8; nt++) {
            const int col = colBase + wn * 64 + nt * 8 + cpair;
            float v00 = acc[mt][nt][0] * alpha;
            float v01 = acc[mt][nt][1] * alpha;
            float v10 = acc[mt][nt][2] * alpha;
            float v11 = acc[mt][nt][3] * alpha;
            if (EPI == 1) {
                const float bx = bias[col], by = bias[col + 1];
                v00 += bx; v01 += by; v10 += bx; v11 += by;
            }
            if (EPI == 2) { v00 += rb0; v01 += rb0; v10 += rb1; v11 += rb1; }
            if (EPI == 3) {
                v00 = __expf(v00) * 0.0625f; v01 = __expf(v01) * 0.0625f;
                v10 = __expf(v10) * 0.0625f; v11 = __expf(v11) * 0.0625f;
                sum0 += v00 + v01; sum1 += v10 + v11;
            }
            if (EPI == 4) { v00 *= rb0; v01 *= rb0; v10 *= rb1; v11 *= rb1; }
            if (EPI == 4) {
                float* Cb = (float*)Cv;
                *reinterpret_cast<float2*>(Cb + r0 * Ntot + col) = make_float2(v00, v01);
                *reinterpret_cast<float2*>(Cb + r1 * Ntot + col) = make_float2(v10, v11);
            } else {
                __half* Cb = (__half*)Cv;
                *reinterpret_cast<__half2*>(Cb + r0 * Ntot + col) = __floats2half2_rn(v00, v01);
                *reinterpret_cast<__half2*>(Cb + r1 * Ntot + col) = __floats2half2_rn(v10, v11);
            }
        }
        if (EPI == 3) {
            sum0 += __shfl_xor_sync(0xFFFFFFFFu, sum0, 1);
            sum0 += __shfl_xor_sync(0xFFFFFFFFu, sum0, 2);
            sum1 += __shfl_xor_sync(0xFFFFFFFFu, sum1, 1);
            sum1 += __shfl_xor_sync(0xFFFFFFFFu, sum1, 2);
            if ((lane & 3) == 0) {
                atomicAdd(aux + r0, sum0);
                atomicAdd(aux + r1, sum1);
            }
        }
    }
}

// ======= merged QKV projection: 1536 linear CTAs (128 threads each) =======
__global__ void __launch_bounds__(NT, 3) proj_kernel(
    const __half* __restrict__ x16, const __half* __restrict__ W16,
    const float* __restrict__ bq, const float* __restrict__ bk, const float* __restrict__ bv,
    __half* __restrict__ Q16, __half* __restrict__ K16, __half* __restrict__ Vt16)
{
    extern __shared__ __align__(1024) char smem[];
    const uint32_t sb = smem_u32(smem);
    const long long SD = (long long)Ss * Dd;
    const long long DD = (long long)Dd * Dd;

    const int cta = blockIdx.x;
    if (cta < 1024) {
        const int z = cta >> 9;
        const int rem = cta & 511;
        const int y = rem >> 3, x = rem & 7;
        gemm_body<1>(x16 + (long long)y * BM * Dd,
                     W16 + z * DD + (long long)x * BN * Dd,
                     z ? bk : bq, nullptr,
                     z ? K16 : Q16, Dd, Dd, 1.0f, y * BM, x * BN, sb);
    } else {
        const int i = cta - 1024;
        const int bz = i >> 7;
        const int rem = i & 127;
        const int y = rem >> 4, x = rem & 15;
        gemm_body<2>(W16 + 2 * DD + (long long)y * BM * Dd,
                     x16 + bz * SD + (long long)x * BN * Dd,
                     bv, nullptr,
                     Vt16 + bz * SD, Ss, Dd, 1.0f, y * BM, x * BN, sb);
    }
}

// ======= scores GEMM: P16 = exp(Q K^T / 32) * 2^-4, row sums fused via atomics =======
__global__ void __launch_bounds__(NT, 3) scores_kernel(
    const __half* __restrict__ Q, const __half* __restrict__ K,
    __half* __restrict__ P, float* __restrict__ rowsum)
{
    extern __shared__ __align__(1024) char smem[];
    const uint32_t sb = smem_u32(smem);
    const long long SD = (long long)Ss * Dd;
    const long long SS2 = (long long)Ss * Ss;
    const int bz = blockIdx.z;
    gemm_body<3>(Q + bz * SD + (long long)blockIdx.y * BM * Dd,
                 K + bz * SD + (long long)blockIdx.x * BN * Dd,
                 nullptr, rowsum + bz * Ss,
                 P + bz * SS2, Ss, Dd, 0.03125f,
                 blockIdx.y * BM, blockIdx.x * BN, sb);
}

// ======= PV GEMM: out = (P16 @ Vt^T) / rowsum[row] =======
__global__ void __launch_bounds__(NT, 3) pv_kernel(
    const __half* __restrict__ P, const __half* __restrict__ Vt,
    const float* __restrict__ rowsum, float* __restrict__ out)
{
    extern __shared__ __align__(1024) char smem[];
    const uint32_t sb = smem_u32(smem);
    const long long SD = (long long)Ss * Dd;
    const long long SS2 = (long long)Ss * Ss;
    const int bz = blockIdx.z;
    gemm_body<4>(P + bz * SS2 + (long long)blockIdx.y * BM * Ss,
                 Vt + bz * SD + (long long)blockIdx.x * BN * Ss,
                 nullptr, const_cast<float*>(rowsum) + bz * Ss,
                 out + bz * SD, Dd, Ss, 1.0f,
                 blockIdx.y * BM, blockIdx.x * BN, sb);
}

// ---------------- merged fp32 -> fp16 convert (x and 3 weights) ----------------
__global__ void cvt_all_kernel(const float* __restrict__ x,
                               const float* __restrict__ wq, const float* __restrict__ wk,
                               const float* __restrict__ wv,
                               __half* __restrict__ x16, __half* __restrict__ W16)
{
    const int b = blockIdx.x;
    const int tid = threadIdx.x;
    const float* src;
    __half* dst;
    int i;
    if (b < 8192) {                 // x: 2097152 float4
        src = x; dst = x16; i = b * 256 + tid;
    } else {                        // weights: 262144 float4 each
        const int wb = b - 8192;
        const int w = wb >> 10;     // 0..2
        src = (w == 0) ? wq : (w == 1) ? wk : wv;
        dst = W16 + (long long)w * Dd * Dd;
        i = (wb & 1023) * 256 + tid;
    }
    const float4 v = reinterpret_cast<const float4*>(src)[i];
    __half2* o = reinterpret_cast<__half2*>(dst);
    o[2 * i]     = __floats2half2_rn(v.x, v.y);
    o[2 * i + 1] = __floats2half2_rn(v.z, v.w);
}

// ---------------- host ----------------
extern "C" void kernel_launch(void* const* d_in, const int* in_sizes, int n_in,
                              void* d_out, int out_size)
{
    const float* x  = (const float*)d_in[0];
    const float* Wq = (const float*)d_in[1];
    const float* bq = (const float*)d_in[2];
    const float* Wk = (const float*)d_in[3];
    const float* bk = (const float*)d_in[4];
    const float* Wv = (const float*)d_in[5];
    const float* bv = (const float*)d_in[6];
    float* out = (float*)d_out;

    __half *x16, *W16, *Q16, *K16, *Vt16, *P16;
    float* rowsum;
    cudaGetSymbolAddress((void**)&x16, g_x16);
    cudaGetSymbolAddress((void**)&W16, g_W16);
    cudaGetSymbolAddress((void**)&Q16, g_Q16);
    cudaGetSymbolAddress((void**)&K16, g_K16);
    cudaGetSymbolAddress((void**)&Vt16, g_Vt16);
    cudaGetSymbolAddress((void**)&P16, g_P16);
    cudaGetSymbolAddress((void**)&rowsum, g_rowsum);

    cudaFuncSetAttribute((const void*)proj_kernel,
                         cudaFuncAttributeMaxDynamicSharedMemorySize, SMEM_BYTES);
    cudaFuncSetAttribute((const void*)scores_kernel,
                         cudaFuncAttributeMaxDynamicSharedMemorySize, SMEM_BYTES);
    cudaFuncSetAttribute((const void*)pv_kernel,
                         cudaFuncAttributeMaxDynamicSharedMemorySize, SMEM_BYTES);

    // 0) zero the fused row-sum accumulator; convert inputs to fp16
    cudaMemsetAsync(rowsum, 0, Bb * Ss * sizeof(float));
    cvt_all_kernel<<<8192 + 3072, 256>>>(x, Wq, Wk, Wv, x16, W16);

    // 1) merged Q/K/Vt projections: one 1536-CTA launch
    proj_kernel<<<1536, NT, SMEM_BYTES>>>(x16, W16, bq, bk, bv, Q16, K16, Vt16);

    // 2) P = exp(Q K^T / 32) * 2^-4 (fp16, unnormalized), row sums accumulated
    const dim3 g2(Ss / BN, Ss / BM, Bb);
    scores_kernel<<<g2, NT, SMEM_BYTES>>>(Q16, K16, P16, rowsum);

    // 3) out = (P @ Vt^T) / rowsum
    const dim3 g3(Dd / BN, Ss / BM, Bb);
    pv_kernel<<<g3, NT, SMEM_BYTES>>>(P16, Vt16, rowsum, out);
}

// round 14
// speedup vs baseline: 1.1886x; 1.1886x over previous
#include <cuda_runtime.h>
#include <cuda_fp16.h>
#include <cstdint>

#define Bb 4
#define Ss 2048
#define Dd 1024

#define BM 128
#define BN 128
#define BK 64                                  // fp16: 64 * 2B = 128B per row
#define A_BYTES (BM * 128)                     // 16KB
#define STAGE_BYTES (2 * A_BYTES)              // 32KB
#define SMEM_BYTES (3 * STAGE_BYTES)           // 96KB, 3 stages (best measured config)
#define NT 128                                 // threads per GEMM CTA (4 warps, 2x2)

// ---------------- device scratch (allocation-free rule) ----------------
__device__ __align__(1024) __half g_x16[Bb * Ss * Dd];
__device__ __align__(1024) __half g_W16[3 * Dd * Dd];
__device__ __align__(1024) __half g_Q16[Bb * Ss * Dd];
__device__ __align__(1024) __half g_K16[Bb * Ss * Dd];
__device__ __align__(1024) __half g_Vt16[Bb * Ss * Dd];
__device__ __align__(1024) __half g_P16[Bb * Ss * Ss];
__device__ float g_rowsum[Bb * Ss];

// ---------------- helpers ----------------
__device__ __forceinline__ uint32_t smem_u32(const void* p) {
    uint32_t a;
    asm("{ .reg .u64 t; cvta.to.shared.u64 t, %1; cvt.u32.u64 %0, t; }" : "=r"(a) : "l"(p));
    return a;
}
__device__ __forceinline__ void cp16(uint32_t dst, const void* src) {
    asm volatile("cp.async.cg.shared.global [%0], [%1], 16;" :: "r"(dst), "l"(src));
}
__device__ __forceinline__ void cp_commit() {
    asm volatile("cp.async.commit_group;" ::: "memory");
}
__device__ __forceinline__ void cp_wait1() {
    asm volatile("cp.async.wait_group 1;" ::: "memory");
}
__device__ __forceinline__ void ldsm4(uint32_t& r0, uint32_t& r1, uint32_t& r2, uint32_t& r3,
                                      uint32_t addr) {
    asm volatile("ldmatrix.sync.aligned.m8n8.x4.shared.b16 {%0,%1,%2,%3}, [%4];"
                 : "=r"(r0), "=r"(r1), "=r"(r2), "=r"(r3) : "r"(addr));
}
__device__ __forceinline__ void mma_f16(float* c, const uint32_t* a, uint32_t b0, uint32_t b1) {
    asm volatile(
        "mma.sync.aligned.m16n8k16.row.col.f32.f16.f16.f32 "
        "{%0,%1,%2,%3}, {%4,%5,%6,%7}, {%8,%9}, {%0,%1,%2,%3};"
        : "+f"(c[0]), "+f"(c[1]), "+f"(c[2]), "+f"(c[3])
        : "r"(a[0]), "r"(a[1]), "r"(a[2]), "r"(a[3]), "r"(b0), "r"(b1));
}

// ======= fp16 mma.sync GEMM body (verbatim best-measured R11 config) =======
// 128 threads, 4 warps 2(M)x2(N), warp tile 64x64, 3-stage cp.async ring, 2 CTAs/SM.
// EPI: 1 = fp16 out, alpha + per-column bias
//      2 = fp16 out, alpha + per-row bias
//      3 = fp16 out, exp(alpha*s)*2^-4, fused row-sum atomicAdd into aux
//      4 = fp32 out, acc * (1/aux[row])          (PV normalize)
template <int EPI>
__device__ __forceinline__ void gemm_body(
    const __half* __restrict__ Ab, const __half* __restrict__ Bg0,
    const float* __restrict__ bias, float* __restrict__ aux,
    void* __restrict__ Cv, int Ntot, int Ktot, float alpha,
    int rowBase, int colBase, uint32_t sb)
{
    const int tid = threadIdx.x;
    const int lane = tid & 31;
    const int wid = tid >> 5;
    const int wm = wid & 1;        // 2 warps in M (64 rows each)
    const int wn = wid >> 1;       // 2 warps in N (64 cols each)

    const int lr = tid >> 3;       // 0..15
    const int lc = tid & 7;        // 0..7
    const uint32_t soff0 = lr * 128 + ((uint32_t)(lc ^ (lr & 7)) << 4);
    const int st16 = 16 * Ktot;
    const __half* pA = Ab + (long long)lr * Ktot + lc * 8;
    const __half* pB = Bg0 + (long long)lr * Ktot + lc * 8;

    const int frow = lane & 15;
    const int fkc = lane >> 4;

    float acc[4][8][4];
#pragma unroll
    for (int i = 0; i < 4; i++)
#pragma unroll
        for (int j = 0; j < 8; j++)
#pragma unroll
            for (int q = 0; q < 4; q++) acc[i][j][q] = 0.0f;

    const int kIters = Ktot / BK;

    auto load_stage = [&](int buf) {
        const uint32_t sbase = sb + buf * STAGE_BYTES + soff0;
#pragma unroll
        for (int p = 0; p < 8; p++) {
            cp16(sbase + p * 2048, pA + p * st16);
            cp16(sbase + A_BYTES + p * 2048, pB + p * st16);
        }
        pA += BK;
        pB += BK;
    };

    load_stage(0); cp_commit();
    load_stage(1); cp_commit();

    int arow[4], brow[4];
#pragma unroll
    for (int mt = 0; mt < 4; mt++) arow[mt] = wm * 64 + mt * 16 + frow;
#pragma unroll
    for (int p = 0; p < 4; p++) brow[p] = wn * 64 + p * 16 + frow;

    int nbuf = 2;
    int cbuf = 0;
    for (int it = 0; it < kIters; it++) {
        cp_wait1();
        __syncthreads();

        if (it + 2 < kIters) load_stage(nbuf);
        cp_commit();
        nbuf = (nbuf + 1 == 3) ? 0 : nbuf + 1;

        const uint32_t As = sb + cbuf * STAGE_BYTES;
        const uint32_t Bs = As + A_BYTES;
        cbuf = (cbuf + 1 == 3) ? 0 : cbuf + 1;

#pragma unroll
        for (int ks = 0; ks < 4; ks++) {
            const int chunk = 2 * ks + fkc;
            uint32_t a[4][4];
#pragma unroll
            for (int mt = 0; mt < 4; mt++) {
                const uint32_t ad = As + arow[mt] * 128 +
                                    ((uint32_t)(chunk ^ (arow[mt] & 7)) << 4);
                ldsm4(a[mt][0], a[mt][1], a[mt][2], a[mt][3], ad);
            }
            uint32_t b[4][4];
#pragma unroll
            for (int p = 0; p < 4; p++) {
                const uint32_t bd = Bs + brow[p] * 128 +
                                    ((uint32_t)(chunk ^ (brow[p] & 7)) << 4);
                ldsm4(b[p][0], b[p][1], b[p][2], b[p][3], bd);
            }
#pragma unroll
            for (int mt = 0; mt < 4; mt++)
#pragma unroll
                for (int nt = 0; nt < 8; nt++) {
                    const int p = nt >> 1, o = nt & 1;
                    mma_f16(acc[mt][nt], a[mt], b[p][o], b[p][2 + o]);
                }
        }
    }

    // ---- epilogue ----
    const int g = lane >> 2;
    const int cpair = (lane & 3) * 2;
#pragma unroll
    for (int mt = 0; mt < 4; mt++) {
        const long long r0 = rowBase + wm * 64 + mt * 16 + g;
        const long long r1 = r0 + 8;
        float rb0 = 0.f, rb1 = 0.f;
        if (EPI == 2) { rb0 = bias[r0]; rb1 = bias[r1]; }
        if (EPI == 4) { rb0 = 1.0f / aux[r0]; rb1 = 1.0f / aux[r1]; }
        float sum0 = 0.f, sum1 = 0.f;
#pragma unroll
        for (int nt = 0; nt < 8; nt++) {
            const int col = colBase + wn * 64 + nt * 8 + cpair;
            float v00 = acc[mt][nt][0] * alpha;
            float v01 = acc[mt][nt][1] * alpha;
            float v10 = acc[mt][nt][2] * alpha;
            float v11 = acc[mt][nt][3] * alpha;
            if (EPI == 1) {
                const float bx = bias[col], by = bias[col + 1];
                v00 += bx; v01 += by; v10 += bx; v11 += by;
            }
            if (EPI == 2) { v00 += rb0; v01 += rb0; v10 += rb1; v11 += rb1; }
            if (EPI == 3) {
                v00 = __expf(v00) * 0.0625f; v01 = __expf(v01) * 0.0625f;
                v10 = __expf(v10) * 0.0625f; v11 = __expf(v11) * 0.0625f;
                sum0 += v00 + v01; sum1 += v10 + v11;
            }
            if (EPI == 4) { v00 *= rb0; v01 *= rb0; v10 *= rb1; v11 *= rb1; }
            if (EPI == 4) {
                float* Cb = (float*)Cv;
                *reinterpret_cast<float2*>(Cb + r0 * Ntot + col) = make_float2(v00, v01);
                *reinterpret_cast<float2*>(Cb + r1 * Ntot + col) = make_float2(v10, v11);
            } else {
                __half* Cb = (__half*)Cv;
                *reinterpret_cast<__half2*>(Cb + r0 * Ntot + col) = __floats2half2_rn(v00, v01);
                *reinterpret_cast<__half2*>(Cb + r1 * Ntot + col) = __floats2half2_rn(v10, v11);
            }
        }
        if (EPI == 3) {
            sum0 += __shfl_xor_sync(0xFFFFFFFFu, sum0, 1);
            sum0 += __shfl_xor_sync(0xFFFFFFFFu, sum0, 2);
            sum1 += __shfl_xor_sync(0xFFFFFFFFu, sum1, 1);
            sum1 += __shfl_xor_sync(0xFFFFFFFFu, sum1, 2);
            if ((lane & 3) == 0) {
                atomicAdd(aux + r0, sum0);
                atomicAdd(aux + r1, sum1);
            }
        }
    }
}

// ======= per-batch QKV projection: 384 CTAs (QK 256 + Vt 128) =======
__global__ void __launch_bounds__(NT, 2) proj_b_kernel(
    int b,
    const __half* __restrict__ x16, const __half* __restrict__ W16,
    const float* __restrict__ bq, const float* __restrict__ bk, const float* __restrict__ bv,
    __half* __restrict__ Q16, __half* __restrict__ K16, __half* __restrict__ Vt16)
{
    extern __shared__ __align__(1024) char smem[];
    const uint32_t sb = smem_u32(smem);
    const long long SD = (long long)Ss * Dd;
    const long long DD = (long long)Dd * Dd;

    const int cta = blockIdx.x;
    if (cta < 256) {
        const int z = cta >> 7;
        const int rem = cta & 127;
        const int y = rem >> 3, x = rem & 7;
        const int rowBase = (b * 16 + y) * BM;
        gemm_body<1>(x16 + (long long)rowBase * Dd,
                     W16 + z * DD + (long long)x * BN * Dd,
                     z ? bk : bq, nullptr,
                     z ? K16 : Q16, Dd, Dd, 1.0f, rowBase, x * BN, sb);
    } else {
        const int i = cta - 256;
        const int y = i >> 4, x = i & 15;
        gemm_body<2>(W16 + 2 * DD + (long long)y * BM * Dd,
                     x16 + b * SD + (long long)x * BN * Dd,
                     bv, nullptr,
                     Vt16 + b * SD, Ss, Dd, 1.0f, y * BM, x * BN, sb);
    }
}

// ======= per-batch scores: P16 = exp(Q K^T / 32) * 2^-4, fused row sums =======
__global__ void __launch_bounds__(NT, 2) scores_b_kernel(
    int b,
    const __half* __restrict__ Q, const __half* __restrict__ K,
    __half* __restrict__ P, float* __restrict__ rowsum)
{
    extern __shared__ __align__(1024) char smem[];
    const uint32_t sb = smem_u32(smem);
    const long long SD = (long long)Ss * Dd;
    const long long SS2 = (long long)Ss * Ss;
    gemm_body<3>(Q + b * SD + (long long)blockIdx.y * BM * Dd,
                 K + b * SD + (long long)blockIdx.x * BN * Dd,
                 nullptr, rowsum + b * Ss,
                 P + b * SS2, Ss, Dd, 0.03125f,
                 blockIdx.y * BM, blockIdx.x * BN, sb);
}

// ======= per-batch PV: out = (P16 @ Vt^T) / rowsum[row] =======
__global__ void __launch_bounds__(NT, 2) pv_b_kernel(
    int b,
    const __half* __restrict__ P, const __half* __restrict__ Vt,
    const float* __restrict__ rowsum, float* __restrict__ out)
{
    extern __shared__ __align__(1024) char smem[];
    const uint32_t sb = smem_u32(smem);
    const long long SD = (long long)Ss * Dd;
    const long long SS2 = (long long)Ss * Ss;
    gemm_body<4>(P + b * SS2 + (long long)blockIdx.y * BM * Ss,
                 Vt + b * SD + (long long)blockIdx.x * BN * Ss,
                 nullptr, const_cast<float*>(rowsum) + b * Ss,
                 out + b * SD, Dd, Ss, 1.0f,
                 blockIdx.y * BM, blockIdx.x * BN, sb);
}

// ---------------- merged fp32 -> fp16 convert (x and 3 weights) ----------------
__global__ void cvt_all_kernel(const float* __restrict__ x,
                               const float* __restrict__ wq, const float* __restrict__ wk,
                               const float* __restrict__ wv,
                               __half* __restrict__ x16, __half* __restrict__ W16)
{
    const int b = blockIdx.x;
    const int tid = threadIdx.x;
    const float* src;
    __half* dst;
    int i;
    if (b < 8192) {
        src = x; dst = x16; i = b * 256 + tid;
    } else {
        const int wb = b - 8192;
        const int w = wb >> 10;
        src = (w == 0) ? wq : (w == 1) ? wk : wv;
        dst = W16 + (long long)w * Dd * Dd;
        i = (wb & 1023) * 256 + tid;
    }
    const float4 v = reinterpret_cast<const float4*>(src)[i];
    __half2* o = reinterpret_cast<__half2*>(dst);
    o[2 * i]     = __floats2half2_rn(v.x, v.y);
    o[2 * i + 1] = __floats2half2_rn(v.z, v.w);
}

// ---------------- host ----------------
extern "C" void kernel_launch(void* const* d_in, const int* in_sizes, int n_in,
                              void* d_out, int out_size)
{
    const float* x  = (const float*)d_in[0];
    const float* Wq = (const float*)d_in[1];
    const float* bq = (const float*)d_in[2];
    const float* Wk = (const float*)d_in[3];
    const float* bk = (const float*)d_in[4];
    const float* Wv = (const float*)d_in[5];
    const float* bv = (const float*)d_in[6];
    float* out = (float*)d_out;

    __half *x16, *W16, *Q16, *K16, *Vt16, *P16;
    float* rowsum;
    cudaGetSymbolAddress((void**)&x16, g_x16);
    cudaGetSymbolAddress((void**)&W16, g_W16);
    cudaGetSymbolAddress((void**)&Q16, g_Q16);
    cudaGetSymbolAddress((void**)&K16, g_K16);
    cudaGetSymbolAddress((void**)&Vt16, g_Vt16);
    cudaGetSymbolAddress((void**)&P16, g_P16);
    cudaGetSymbolAddress((void**)&rowsum, g_rowsum);

    cudaFuncSetAttribute((const void*)proj_b_kernel,
                         cudaFuncAttributeMaxDynamicSharedMemorySize, SMEM_BYTES);
    cudaFuncSetAttribute((const void*)scores_b_kernel,
                         cudaFuncAttributeMaxDynamicSharedMemorySize, SMEM_BYTES);
    cudaFuncSetAttribute((const void*)pv_b_kernel,
                         cudaFuncAttributeMaxDynamicSharedMemorySize, SMEM_BYTES);

    // One-time side-stream / event creation (host resources only, no device
    // memory; work per call is identical and deterministic).
    static cudaStream_t s1 = nullptr;
    static cudaEvent_t eFork = nullptr, eJoin = nullptr;
    if (s1 == nullptr) {
        cudaStreamCreateWithFlags(&s1, cudaStreamNonBlocking);
        cudaEventCreateWithFlags(&eFork, cudaEventDisableTiming);
        cudaEventCreateWithFlags(&eJoin, cudaEventDisableTiming);
    }

    const dim3 gS(Ss / BN, Ss / BM);   // 16x16 per batch
    const dim3 gP(Dd / BN, Ss / BM);   // 8x16 per batch

    // 0) prep on the origin (default) stream
    cudaMemsetAsync(rowsum, 0, Bb * Ss * sizeof(float));
    cvt_all_kernel<<<8192 + 3072, 256>>>(x, Wq, Wk, Wv, x16, W16);

    // fork: side stream s1 depends on prep
    cudaEventRecord(eFork, 0);
    cudaStreamWaitEvent(s1, eFork, 0);

    // Two pipelined batch chains: batches 0,2 on the origin stream; 1,3 on s1.
    // Each chain: proj(b) -> scores(b) -> pv(b) -> proj(b+2) -> ...
    // Co-residency fills the partial waves each phase leaves (pv = 128 CTAs,
    // scores = 256, proj = 384, vs 296 concurrent CTA slots).
    for (int p = 0; p < 2; p++) {
        const int b0 = p * 2;       // origin-stream batch
        const int b1 = p * 2 + 1;   // s1 batch
        proj_b_kernel<<<384, NT, SMEM_BYTES>>>(b0, x16, W16, bq, bk, bv, Q16, K16, Vt16);
        proj_b_kernel<<<384, NT, SMEM_BYTES, s1>>>(b1, x16, W16, bq, bk, bv, Q16, K16, Vt16);
        scores_b_kernel<<<gS, NT, SMEM_BYTES>>>(b0, Q16, K16, P16, rowsum);
        scores_b_kernel<<<gS, NT, SMEM_BYTES, s1>>>(b1, Q16, K16, P16, rowsum);
        pv_b_kernel<<<gP, NT, SMEM_BYTES>>>(b0, P16, Vt16, rowsum, out);
        pv_b_kernel<<<gP, NT, SMEM_BYTES, s1>>>(b1, P16, Vt16, rowsum, out);
    }

    // join: origin stream waits for s1's chain
    cudaEventRecord(eJoin, s1);
    cudaStreamWaitEvent(0, eJoin, 0);
}

// round 15
// speedup vs baseline: 1.2277x; 1.0329x over previous
#include <cuda_runtime.h>
#include <cuda_fp16.h>
#include <cstdint>

#define Bb 4
#define Ss 2048
#define Dd 1024

#define BM 128
#define BN 128
#define BK 64                                  // fp16: 64 * 2B = 128B per row
#define A_BYTES (BM * 128)                     // 16KB
#define STAGE_BYTES (2 * A_BYTES)              // 32KB
#define SMEM_BYTES (3 * STAGE_BYTES)           // 96KB, 3 stages (best measured config)
#define NT 128                                 // threads per GEMM CTA (4 warps, 2x2)

// ---------------- device scratch (allocation-free rule) ----------------
__device__ __align__(1024) __half g_x16[Bb * Ss * Dd];
__device__ __align__(1024) __half g_W16[3 * Dd * Dd];
__device__ __align__(1024) __half g_Q16[Bb * Ss * Dd];
__device__ __align__(1024) __half g_K16[Bb * Ss * Dd];
__device__ __align__(1024) __half g_Vt16[Bb * Ss * Dd];
__device__ __align__(1024) __half g_P16[Bb * Ss * Ss];
__device__ float g_rowsum[Bb * Ss];

// ---------------- helpers ----------------
__device__ __forceinline__ uint32_t smem_u32(const void* p) {
    uint32_t a;
    asm("{ .reg .u64 t; cvta.to.shared.u64 t, %1; cvt.u32.u64 %0, t; }" : "=r"(a) : "l"(p));
    return a;
}
__device__ __forceinline__ void cp16(uint32_t dst, const void* src) {
    asm volatile("cp.async.cg.shared.global [%0], [%1], 16;" :: "r"(dst), "l"(src));
}
__device__ __forceinline__ void cp_commit() {
    asm volatile("cp.async.commit_group;" ::: "memory");
}
__device__ __forceinline__ void cp_wait1() {
    asm volatile("cp.async.wait_group 1;" ::: "memory");
}
__device__ __forceinline__ void ldsm4(uint32_t& r0, uint32_t& r1, uint32_t& r2, uint32_t& r3,
                                      uint32_t addr) {
    asm volatile("ldmatrix.sync.aligned.m8n8.x4.shared.b16 {%0,%1,%2,%3}, [%4];"
                 : "=r"(r0), "=r"(r1), "=r"(r2), "=r"(r3) : "r"(addr));
}
__device__ __forceinline__ void mma_f16(float* c, const uint32_t* a, uint32_t b0, uint32_t b1) {
    asm volatile(
        "mma.sync.aligned.m16n8k16.row.col.f32.f16.f16.f32 "
        "{%0,%1,%2,%3}, {%4,%5,%6,%7}, {%8,%9}, {%0,%1,%2,%3};"
        : "+f"(c[0]), "+f"(c[1]), "+f"(c[2]), "+f"(c[3])
        : "r"(a[0]), "r"(a[1]), "r"(a[2]), "r"(a[3]), "r"(b0), "r"(b1));
}

// ======= fp16 mma.sync GEMM body (verbatim best-measured R11 config) =======
// 128 threads, 4 warps 2(M)x2(N), warp tile 64x64, 3-stage cp.async ring, 2 CTAs/SM.
// EPI: 1 = fp16 out, alpha + per-column bias
//      2 = fp16 out, alpha + per-row bias
//      3 = fp16 out, exp(alpha*s)*2^-4, fused row-sum atomicAdd into aux
//      4 = fp32 out, acc * (1/aux[row])          (PV normalize)
template <int EPI>
__device__ __forceinline__ void gemm_body(
    const __half* __restrict__ Ab, const __half* __restrict__ Bg0,
    const float* __restrict__ bias, float* __restrict__ aux,
    void* __restrict__ Cv, int Ntot, int Ktot, float alpha,
    int rowBase, int colBase, uint32_t sb)
{
    const int tid = threadIdx.x;
    const int lane = tid & 31;
    const int wid = tid >> 5;
    const int wm = wid & 1;        // 2 warps in M (64 rows each)
    const int wn = wid >> 1;       // 2 warps in N (64 cols each)

    const int lr = tid >> 3;       // 0..15
    const int lc = tid & 7;        // 0..7
    const uint32_t soff0 = lr * 128 + ((uint32_t)(lc ^ (lr & 7)) << 4);
    const int st16 = 16 * Ktot;
    const __half* pA = Ab + (long long)lr * Ktot + lc * 8;
    const __half* pB = Bg0 + (long long)lr * Ktot + lc * 8;

    const int frow = lane & 15;
    const int fkc = lane >> 4;

    float acc[4][8][4];
#pragma unroll
    for (int i = 0; i < 4; i++)
#pragma unroll
        for (int j = 0; j < 8; j++)
#pragma unroll
            for (int q = 0; q < 4; q++) acc[i][j][q] = 0.0f;

    const int kIters = Ktot / BK;

    auto load_stage = [&](int buf) {
        const uint32_t sbase = sb + buf * STAGE_BYTES + soff0;
#pragma unroll
        for (int p = 0; p < 8; p++) {
            cp16(sbase + p * 2048, pA + p * st16);
            cp16(sbase + A_BYTES + p * 2048, pB + p * st16);
        }
        pA += BK;
        pB += BK;
    };

    load_stage(0); cp_commit();
    load_stage(1); cp_commit();

    int arow[4], brow[4];
#pragma unroll
    for (int mt = 0; mt < 4; mt++) arow[mt] = wm * 64 + mt * 16 + frow;
#pragma unroll
    for (int p = 0; p < 4; p++) brow[p] = wn * 64 + p * 16 + frow;

    int nbuf = 2;
    int cbuf = 0;
    for (int it = 0; it < kIters; it++) {
        cp_wait1();
        __syncthreads();

        if (it + 2 < kIters) load_stage(nbuf);
        cp_commit();
        nbuf = (nbuf + 1 == 3) ? 0 : nbuf + 1;

        const uint32_t As = sb + cbuf * STAGE_BYTES;
        const uint32_t Bs = As + A_BYTES;
        cbuf = (cbuf + 1 == 3) ? 0 : cbuf + 1;

#pragma unroll
        for (int ks = 0; ks < 4; ks++) {
            const int chunk = 2 * ks + fkc;
            uint32_t a[4][4];
#pragma unroll
            for (int mt = 0; mt < 4; mt++) {
                const uint32_t ad = As + arow[mt] * 128 +
                                    ((uint32_t)(chunk ^ (arow[mt] & 7)) << 4);
                ldsm4(a[mt][0], a[mt][1], a[mt][2], a[mt][3], ad);
            }
            uint32_t b[4][4];
#pragma unroll
            for (int p = 0; p < 4; p++) {
                const uint32_t bd = Bs + brow[p] * 128 +
                                    ((uint32_t)(chunk ^ (brow[p] & 7)) << 4);
                ldsm4(b[p][0], b[p][1], b[p][2], b[p][3], bd);
            }
#pragma unroll
            for (int mt = 0; mt < 4; mt++)
#pragma unroll
                for (int nt = 0; nt < 8; nt++) {
                    const int p = nt >> 1, o = nt & 1;
                    mma_f16(acc[mt][nt], a[mt], b[p][o], b[p][2 + o]);
                }
        }
    }

    // ---- epilogue ----
    const int g = lane >> 2;
    const int cpair = (lane & 3) * 2;
#pragma unroll
    for (int mt = 0; mt < 4; mt++) {
        const long long r0 = rowBase + wm * 64 + mt * 16 + g;
        const long long r1 = r0 + 8;
        float rb0 = 0.f, rb1 = 0.f;
        if (EPI == 2) { rb0 = bias[r0]; rb1 = bias[r1]; }
        if (EPI == 4) { rb0 = 1.0f / aux[r0]; rb1 = 1.0f / aux[r1]; }
        float sum0 = 0.f, sum1 = 0.f;
#pragma unroll
        for (int nt = 0; nt < 8; nt++) {
            const int col = colBase + wn * 64 + nt * 8 + cpair;
            float v00 = acc[mt][nt][0] * alpha;
            float v01 = acc[mt][nt][1] * alpha;
            float v10 = acc[mt][nt][2] * alpha;
            float v11 = acc[mt][nt][3] * alpha;
            if (EPI == 1) {
                const float bx = bias[col], by = bias[col + 1];
                v00 += bx; v01 += by; v10 += bx; v11 += by;
            }
            if (EPI == 2) { v00 += rb0; v01 += rb0; v10 += rb1; v11 += rb1; }
            if (EPI == 3) {
                v00 = __expf(v00) * 0.0625f; v01 = __expf(v01) * 0.0625f;
                v10 = __expf(v10) * 0.0625f; v11 = __expf(v11) * 0.0625f;
                sum0 += v00 + v01; sum1 += v10 + v11;
            }
            if (EPI == 4) { v00 *= rb0; v01 *= rb0; v10 *= rb1; v11 *= rb1; }
            if (EPI == 4) {
                float* Cb = (float*)Cv;
                *reinterpret_cast<float2*>(Cb + r0 * Ntot + col) = make_float2(v00, v01);
                *reinterpret_cast<float2*>(Cb + r1 * Ntot + col) = make_float2(v10, v11);
            } else {
                __half* Cb = (__half*)Cv;
                *reinterpret_cast<__half2*>(Cb + r0 * Ntot + col) = __floats2half2_rn(v00, v01);
                *reinterpret_cast<__half2*>(Cb + r1 * Ntot + col) = __floats2half2_rn(v10, v11);
            }
        }
        if (EPI == 3) {
            sum0 += __shfl_xor_sync(0xFFFFFFFFu, sum0, 1);
            sum0 += __shfl_xor_sync(0xFFFFFFFFu, sum0, 2);
            sum1 += __shfl_xor_sync(0xFFFFFFFFu, sum1, 1);
            sum1 += __shfl_xor_sync(0xFFFFFFFFu, sum1, 2);
            if ((lane & 3) == 0) {
                atomicAdd(aux + r0, sum0);
                atomicAdd(aux + r1, sum1);
            }
        }
    }
}

// ======= per-batch QKV projection: 384 CTAs (QK 256 + Vt 128) =======
__global__ void __launch_bounds__(NT, 2) proj_b_kernel(
    int b,
    const __half* __restrict__ x16, const __half* __restrict__ W16,
    const float* __restrict__ bq, const float* __restrict__ bk, const float* __restrict__ bv,
    __half* __restrict__ Q16, __half* __restrict__ K16, __half* __restrict__ Vt16)
{
    extern __shared__ __align__(1024) char smem[];
    const uint32_t sb = smem_u32(smem);
    const long long SD = (long long)Ss * Dd;
    const long long DD = (long long)Dd * Dd;

    const int cta = blockIdx.x;
    if (cta < 256) {
        const int z = cta >> 7;
        const int rem = cta & 127;
        const int y = rem >> 3, x = rem & 7;
        const int rowBase = (b * 16 + y) * BM;
        gemm_body<1>(x16 + (long long)rowBase * Dd,
                     W16 + z * DD + (long long)x * BN * Dd,
                     z ? bk : bq, nullptr,
                     z ? K16 : Q16, Dd, Dd, 1.0f, rowBase, x * BN, sb);
    } else {
        const int i = cta - 256;
        const int y = i >> 4, x = i & 15;
        gemm_body<2>(W16 + 2 * DD + (long long)y * BM * Dd,
                     x16 + b * SD + (long long)x * BN * Dd,
                     bv, nullptr,
                     Vt16 + b * SD, Ss, Dd, 1.0f, y * BM, x * BN, sb);
    }
}

// ======= per-batch scores: P16 = exp(Q K^T / 32) * 2^-4, fused row sums =======
__global__ void __launch_bounds__(NT, 2) scores_b_kernel(
    int b,
    const __half* __restrict__ Q, const __half* __restrict__ K,
    __half* __restrict__ P, float* __restrict__ rowsum)
{
    extern __shared__ __align__(1024) char smem[];
    const uint32_t sb = smem_u32(smem);
    const long long SD = (long long)Ss * Dd;
    const long long SS2 = (long long)Ss * Ss;
    gemm_body<3>(Q + b * SD + (long long)blockIdx.y * BM * Dd,
                 K + b * SD + (long long)blockIdx.x * BN * Dd,
                 nullptr, rowsum + b * Ss,
                 P + b * SS2, Ss, Dd, 0.03125f,
                 blockIdx.y * BM, blockIdx.x * BN, sb);
}

// ======= per-batch PV: out = (P16 @ Vt^T) / rowsum[row] =======
__global__ void __launch_bounds__(NT, 2) pv_b_kernel(
    int b,
    const __half* __restrict__ P, const __half* __restrict__ Vt,
    const float* __restrict__ rowsum, float* __restrict__ out)
{
    extern __shared__ __align__(1024) char smem[];
    const uint32_t sb = smem_u32(smem);
    const long long SD = (long long)Ss * Dd;
    const long long SS2 = (long long)Ss * Ss;
    gemm_body<4>(P + b * SS2 + (long long)blockIdx.y * BM * Ss,
                 Vt + b * SD + (long long)blockIdx.x * BN * Ss,
                 nullptr, const_cast<float*>(rowsum) + b * Ss,
                 out + b * SD, Dd, Ss, 1.0f,
                 blockIdx.y * BM, blockIdx.x * BN, sb);
}

// ---------------- merged fp32 -> fp16 convert (x and 3 weights) ----------------
__global__ void cvt_all_kernel(const float* __restrict__ x,
                               const float* __restrict__ wq, const float* __restrict__ wk,
                               const float* __restrict__ wv,
                               __half* __restrict__ x16, __half* __restrict__ W16)
{
    const int b = blockIdx.x;
    const int tid = threadIdx.x;
    const float* src;
    __half* dst;
    int i;
    if (b < 8192) {
        src = x; dst = x16; i = b * 256 + tid;
    } else {
        const int wb = b - 8192;
        const int w = wb >> 10;
        src = (w == 0) ? wq : (w == 1) ? wk : wv;
        dst = W16 + (long long)w * Dd * Dd;
        i = (wb & 1023) * 256 + tid;
    }
    const float4 v = reinterpret_cast<const float4*>(src)[i];
    __half2* o = reinterpret_cast<__half2*>(dst);
    o[2 * i]     = __floats2half2_rn(v.x, v.y);
    o[2 * i + 1] = __floats2half2_rn(v.z, v.w);
}

// ---------------- host ----------------
extern "C" void kernel_launch(void* const* d_in, const int* in_sizes, int n_in,
                              void* d_out, int out_size)
{
    const float* x  = (const float*)d_in[0];
    const float* Wq = (const float*)d_in[1];
    const float* bq = (const float*)d_in[2];
    const float* Wk = (const float*)d_in[3];
    const float* bk = (const float*)d_in[4];
    const float* Wv = (const float*)d_in[5];
    const float* bv = (const float*)d_in[6];
    float* out = (float*)d_out;

    __half *x16, *W16, *Q16, *K16, *Vt16, *P16;
    float* rowsum;
    cudaGetSymbolAddress((void**)&x16, g_x16);
    cudaGetSymbolAddress((void**)&W16, g_W16);
    cudaGetSymbolAddress((void**)&Q16, g_Q16);
    cudaGetSymbolAddress((void**)&K16, g_K16);
    cudaGetSymbolAddress((void**)&Vt16, g_Vt16);
    cudaGetSymbolAddress((void**)&P16, g_P16);
    cudaGetSymbolAddress((void**)&rowsum, g_rowsum);

    cudaFuncSetAttribute((const void*)proj_b_kernel,
                         cudaFuncAttributeMaxDynamicSharedMemorySize, SMEM_BYTES);
    cudaFuncSetAttribute((const void*)scores_b_kernel,
                         cudaFuncAttributeMaxDynamicSharedMemorySize, SMEM_BYTES);
    cudaFuncSetAttribute((const void*)pv_b_kernel,
                         cudaFuncAttributeMaxDynamicSharedMemorySize, SMEM_BYTES);

    // One-time side-stream / event creation (host resources only, no device
    // memory; work per call is identical and deterministic).
    static cudaStream_t st[3] = {nullptr, nullptr, nullptr};
    static cudaEvent_t eFork = nullptr;
    static cudaEvent_t eJoin[3] = {nullptr, nullptr, nullptr};
    if (st[0] == nullptr) {
        for (int i = 0; i < 3; i++) {
            cudaStreamCreateWithFlags(&st[i], cudaStreamNonBlocking);
            cudaEventCreateWithFlags(&eJoin[i], cudaEventDisableTiming);
        }
        cudaEventCreateWithFlags(&eFork, cudaEventDisableTiming);
    }

    const dim3 gS(Ss / BN, Ss / BM);   // 16x16 per batch
    const dim3 gP(Dd / BN, Ss / BM);   // 8x16 per batch

    // 0) prep on the origin (default) stream
    cudaMemsetAsync(rowsum, 0, Bb * Ss * sizeof(float));
    cvt_all_kernel<<<8192 + 3072, 256>>>(x, Wq, Wk, Wv, x16, W16);

    // fork: side streams depend on prep
    cudaEventRecord(eFork, 0);
    for (int i = 0; i < 3; i++) cudaStreamWaitEvent(st[i], eFork, 0);

    // Four independent batch chains, one per stream (batch 0 on the origin
    // stream). Each chain proj(b)->scores(b)->pv(b); co-residency across
    // chains fills every phase's partial waves and launch gaps.
    for (int b = 0; b < Bb; b++) {
        cudaStream_t s = (b == 0) ? (cudaStream_t)0 : st[b - 1];
        proj_b_kernel<<<384, NT, SMEM_BYTES, s>>>(b, x16, W16, bq, bk, bv, Q16, K16, Vt16);
        scores_b_kernel<<<gS, NT, SMEM_BYTES, s>>>(b, Q16, K16, P16, rowsum);
        pv_b_kernel<<<gP, NT, SMEM_BYTES, s>>>(b, P16, Vt16, rowsum, out);
    }

    // join: origin stream waits for all side chains
    for (int i = 0; i < 3; i++) {
        cudaEventRecord(eJoin[i], st[i]);
        cudaStreamWaitEvent(0, eJoin[i], 0);
    }
}

// round 16
// speedup vs baseline: 1.2325x; 1.0039x over previous
#include <cuda_runtime.h>
#include <cuda_fp16.h>
#include <cstdint>

#define Bb 4
#define Ss 2048
#define Dd 1024

#define BM 128
#define BN 128
#define BK 64                                  // fp16: 64 * 2B = 128B per row
#define A_BYTES (BM * 128)                     // 16KB
#define STAGE_BYTES (2 * A_BYTES)              // 32KB
#define SMEM_BYTES (3 * STAGE_BYTES)           // 96KB, 3 stages (best measured config)
#define NT 128                                 // threads per GEMM CTA (4 warps, 2x2)

// ---------------- device scratch (allocation-free rule) ----------------
__device__ __align__(1024) __half g_x16[Bb * Ss * Dd];
__device__ __align__(1024) __half g_W16[3 * Dd * Dd];
__device__ __align__(1024) __half g_Q16[Bb * Ss * Dd];
__device__ __align__(1024) __half g_K16[Bb * Ss * Dd];
__device__ __align__(1024) __half g_Vt16[Bb * Ss * Dd];
__device__ __align__(1024) __half g_P16[Bb * Ss * Ss];
__device__ float g_rowsum[Bb * Ss];

// ---------------- helpers ----------------
__device__ __forceinline__ uint32_t smem_u32(const void* p) {
    uint32_t a;
    asm("{ .reg .u64 t; cvta.to.shared.u64 t, %1; cvt.u32.u64 %0, t; }" : "=r"(a) : "l"(p));
    return a;
}
__device__ __forceinline__ void cp16(uint32_t dst, const void* src) {
    asm volatile("cp.async.cg.shared.global [%0], [%1], 16;" :: "r"(dst), "l"(src));
}
__device__ __forceinline__ void cp_commit() {
    asm volatile("cp.async.commit_group;" ::: "memory");
}
__device__ __forceinline__ void cp_wait1() {
    asm volatile("cp.async.wait_group 1;" ::: "memory");
}
__device__ __forceinline__ void ldsm4(uint32_t& r0, uint32_t& r1, uint32_t& r2, uint32_t& r3,
                                      uint32_t addr) {
    asm volatile("ldmatrix.sync.aligned.m8n8.x4.shared.b16 {%0,%1,%2,%3}, [%4];"
                 : "=r"(r0), "=r"(r1), "=r"(r2), "=r"(r3) : "r"(addr));
}
__device__ __forceinline__ void mma_f16(float* c, const uint32_t* a, uint32_t b0, uint32_t b1) {
    asm volatile(
        "mma.sync.aligned.m16n8k16.row.col.f32.f16.f16.f32 "
        "{%0,%1,%2,%3}, {%4,%5,%6,%7}, {%8,%9}, {%0,%1,%2,%3};"
        : "+f"(c[0]), "+f"(c[1]), "+f"(c[2]), "+f"(c[3])
        : "r"(a[0]), "r"(a[1]), "r"(a[2]), "r"(a[3]), "r"(b0), "r"(b1));
}

// ======= fp16 mma.sync GEMM body (verbatim best-measured R11 config) =======
// 128 threads, 4 warps 2(M)x2(N), warp tile 64x64, 3-stage cp.async ring, 2 CTAs/SM.
// EPI: 1 = fp16 out, alpha + per-column bias
//      2 = fp16 out, alpha + per-row bias
//      3 = fp16 out, exp(alpha*s)*2^-4, fused row-sum atomicAdd into aux
//      4 = fp32 out, acc * (1/aux[row])          (PV normalize)
template <int EPI>
__device__ __forceinline__ void gemm_body(
    const __half* __restrict__ Ab, const __half* __restrict__ Bg0,
    const float* __restrict__ bias, float* __restrict__ aux,
    void* __restrict__ Cv, int Ntot, int Ktot, float alpha,
    int rowBase, int colBase, uint32_t sb)
{
    const int tid = threadIdx.x;
    const int lane = tid & 31;
    const int wid = tid >> 5;
    const int wm = wid & 1;        // 2 warps in M (64 rows each)
    const int wn = wid >> 1;       // 2 warps in N (64 cols each)

    const int lr = tid >> 3;       // 0..15
    const int lc = tid & 7;        // 0..7
    const uint32_t soff0 = lr * 128 + ((uint32_t)(lc ^ (lr & 7)) << 4);
    const int st16 = 16 * Ktot;
    const __half* pA = Ab + (long long)lr * Ktot + lc * 8;
    const __half* pB = Bg0 + (long long)lr * Ktot + lc * 8;

    const int frow = lane & 15;
    const int fkc = lane >> 4;

    float acc[4][8][4];
#pragma unroll
    for (int i = 0; i < 4; i++)
#pragma unroll
        for (int j = 0; j < 8; j++)
#pragma unroll
            for (int q = 0; q < 4; q++) acc[i][j][q] = 0.0f;

    const int kIters = Ktot / BK;

    auto load_stage = [&](int buf) {
        const uint32_t sbase = sb + buf * STAGE_BYTES + soff0;
#pragma unroll
        for (int p = 0; p < 8; p++) {
            cp16(sbase + p * 2048, pA + p * st16);
            cp16(sbase + A_BYTES + p * 2048, pB + p * st16);
        }
        pA += BK;
        pB += BK;
    };

    load_stage(0); cp_commit();
    load_stage(1); cp_commit();

    int arow[4], brow[4];
#pragma unroll
    for (int mt = 0; mt < 4; mt++) arow[mt] = wm * 64 + mt * 16 + frow;
#pragma unroll
    for (int p = 0; p < 4; p++) brow[p] = wn * 64 + p * 16 + frow;

    int nbuf = 2;
    int cbuf = 0;
    for (int it = 0; it < kIters; it++) {
        cp_wait1();
        __syncthreads();

        if (it + 2 < kIters) load_stage(nbuf);
        cp_commit();
        nbuf = (nbuf + 1 == 3) ? 0 : nbuf + 1;

        const uint32_t As = sb + cbuf * STAGE_BYTES;
        const uint32_t Bs = As + A_BYTES;
        cbuf = (cbuf + 1 == 3) ? 0 : cbuf + 1;

#pragma unroll
        for (int ks = 0; ks < 4; ks++) {
            const int chunk = 2 * ks + fkc;
            uint32_t a[4][4];
#pragma unroll
            for (int mt = 0; mt < 4; mt++) {
                const uint32_t ad = As + arow[mt] * 128 +
                                    ((uint32_t)(chunk ^ (arow[mt] & 7)) << 4);
                ldsm4(a[mt][0], a[mt][1], a[mt][2], a[mt][3], ad);
            }
            uint32_t b[4][4];
#pragma unroll
            for (int p = 0; p < 4; p++) {
                const uint32_t bd = Bs + brow[p] * 128 +
                                    ((uint32_t)(chunk ^ (brow[p] & 7)) << 4);
                ldsm4(b[p][0], b[p][1], b[p][2], b[p][3], bd);
            }
#pragma unroll
            for (int mt = 0; mt < 4; mt++)
#pragma unroll
                for (int nt = 0; nt < 8; nt++) {
                    const int p = nt >> 1, o = nt & 1;
                    mma_f16(acc[mt][nt], a[mt], b[p][o], b[p][2 + o]);
                }
        }
    }

    // ---- epilogue ----
    const int g = lane >> 2;
    const int cpair = (lane & 3) * 2;
#pragma unroll
    for (int mt = 0; mt < 4; mt++) {
        const long long r0 = rowBase + wm * 64 + mt * 16 + g;
        const long long r1 = r0 + 8;
        float rb0 = 0.f, rb1 = 0.f;
        if (EPI == 2) { rb0 = bias[r0]; rb1 = bias[r1]; }
        if (EPI == 4) { rb0 = 1.0f / aux[r0]; rb1 = 1.0f / aux[r1]; }
        float sum0 = 0.f, sum1 = 0.f;
#pragma unroll
        for (int nt = 0; nt < 8; nt++) {
            const int col = colBase + wn * 64 + nt * 8 + cpair;
            float v00 = acc[mt][nt][0] * alpha;
            float v01 = acc[mt][nt][1] * alpha;
            float v10 = acc[mt][nt][2] * alpha;
            float v11 = acc[mt][nt][3] * alpha;
            if (EPI == 1) {
                const float bx = bias[col], by = bias[col + 1];
                v00 += bx; v01 += by; v10 += bx; v11 += by;
            }
            if (EPI == 2) { v00 += rb0; v01 += rb0; v10 += rb1; v11 += rb1; }
            if (EPI == 3) {
                v00 = __expf(v00) * 0.0625f; v01 = __expf(v01) * 0.0625f;
                v10 = __expf(v10) * 0.0625f; v11 = __expf(v11) * 0.0625f;
                sum0 += v00 + v01; sum1 += v10 + v11;
            }
            if (EPI == 4) { v00 *= rb0; v01 *= rb0; v10 *= rb1; v11 *= rb1; }
            if (EPI == 4) {
                float* Cb = (float*)Cv;
                *reinterpret_cast<float2*>(Cb + r0 * Ntot + col) = make_float2(v00, v01);
                *reinterpret_cast<float2*>(Cb + r1 * Ntot + col) = make_float2(v10, v11);
            } else {
                __half* Cb = (__half*)Cv;
                *reinterpret_cast<__half2*>(Cb + r0 * Ntot + col) = __floats2half2_rn(v00, v01);
                *reinterpret_cast<__half2*>(Cb + r1 * Ntot + col) = __floats2half2_rn(v10, v11);
            }
        }
        if (EPI == 3) {
            sum0 += __shfl_xor_sync(0xFFFFFFFFu, sum0, 1);
            sum0 += __shfl_xor_sync(0xFFFFFFFFu, sum0, 2);
            sum1 += __shfl_xor_sync(0xFFFFFFFFu, sum1, 1);
            sum1 += __shfl_xor_sync(0xFFFFFFFFu, sum1, 2);
            if ((lane & 3) == 0) {
                atomicAdd(aux + r0, sum0);
                atomicAdd(aux + r1, sum1);
            }
        }
    }
}

// ======= per-batch QKV projection: 384 CTAs (QK 256 + Vt 128) =======
__global__ void __launch_bounds__(NT, 2) proj_b_kernel(
    int b,
    const __half* __restrict__ x16, const __half* __restrict__ W16,
    const float* __restrict__ bq, const float* __restrict__ bk, const float* __restrict__ bv,
    __half* __restrict__ Q16, __half* __restrict__ K16, __half* __restrict__ Vt16)
{
    extern __shared__ __align__(1024) char smem[];
    const uint32_t sb = smem_u32(smem);
    const long long SD = (long long)Ss * Dd;
    const long long DD = (long long)Dd * Dd;

    const int cta = blockIdx.x;
    if (cta < 256) {
        const int z = cta >> 7;
        const int rem = cta & 127;
        const int y = rem >> 3, x = rem & 7;
        const int rowBase = (b * 16 + y) * BM;
        gemm_body<1>(x16 + (long long)rowBase * Dd,
                     W16 + z * DD + (long long)x * BN * Dd,
                     z ? bk : bq, nullptr,
                     z ? K16 : Q16, Dd, Dd, 1.0f, rowBase, x * BN, sb);
    } else {
        const int i = cta - 256;
        const int y = i >> 4, x = i & 15;
        gemm_body<2>(W16 + 2 * DD + (long long)y * BM * Dd,
                     x16 + b * SD + (long long)x * BN * Dd,
                     bv, nullptr,
                     Vt16 + b * SD, Ss, Dd, 1.0f, y * BM, x * BN, sb);
    }
}

// ======= per-batch scores: P16 = exp(Q K^T / 32) * 2^-4, fused row sums =======
__global__ void __launch_bounds__(NT, 2) scores_b_kernel(
    int b,
    const __half* __restrict__ Q, const __half* __restrict__ K,
    __half* __restrict__ P, float* __restrict__ rowsum)
{
    extern __shared__ __align__(1024) char smem[];
    const uint32_t sb = smem_u32(smem);
    const long long SD = (long long)Ss * Dd;
    const long long SS2 = (long long)Ss * Ss;
    gemm_body<3>(Q + b * SD + (long long)blockIdx.y * BM * Dd,
                 K + b * SD + (long long)blockIdx.x * BN * Dd,
                 nullptr, rowsum + b * Ss,
                 P + b * SS2, Ss, Dd, 0.03125f,
                 blockIdx.y * BM, blockIdx.x * BN, sb);
}

// ======= per-batch PV: out = (P16 @ Vt^T) / rowsum[row] =======
__global__ void __launch_bounds__(NT, 2) pv_b_kernel(
    int b,
    const __half* __restrict__ P, const __half* __restrict__ Vt,
    const float* __restrict__ rowsum, float* __restrict__ out)
{
    extern __shared__ __align__(1024) char smem[];
    const uint32_t sb = smem_u32(smem);
    const long long SD = (long long)Ss * Dd;
    const long long SS2 = (long long)Ss * Ss;
    gemm_body<4>(P + b * SS2 + (long long)blockIdx.y * BM * Ss,
                 Vt + b * SD + (long long)blockIdx.x * BN * Ss,
                 nullptr, const_cast<float*>(rowsum) + b * Ss,
                 out + b * SD, Dd, Ss, 1.0f,
                 blockIdx.y * BM, blockIdx.x * BN, sb);
}

// ---------------- fp32 -> fp16 weight convert (3 weights, shared prologue) ----------------
__global__ void cvt_w_kernel(const float* __restrict__ wq, const float* __restrict__ wk,
                             const float* __restrict__ wv, __half* __restrict__ W16)
{
    const int wb = blockIdx.x;          // 0..3071
    const int w = wb >> 10;             // 0..2
    const float* src = (w == 0) ? wq : (w == 1) ? wk : wv;
    __half* dst = W16 + (long long)w * Dd * Dd;
    const int i = (wb & 1023) * 256 + threadIdx.x;
    const float4 v = reinterpret_cast<const float4*>(src)[i];
    __half2* o = reinterpret_cast<__half2*>(dst);
    o[2 * i]     = __floats2half2_rn(v.x, v.y);
    o[2 * i + 1] = __floats2half2_rn(v.z, v.w);
}

// ---------------- per-batch x-slice convert + rowsum zero (chain head) ----------------
__global__ void cvt_x_b_kernel(int b, const float* __restrict__ x,
                               __half* __restrict__ x16, float* __restrict__ rowsum)
{
    const long long base = (long long)b * (Ss * Dd / 4);   // float4 index base
    const int i = blockIdx.x * 256 + threadIdx.x;           // 0..524287
    const float4 v = reinterpret_cast<const float4*>(x)[base + i];
    __half2* o = reinterpret_cast<__half2*>(x16);
    o[2 * (base + i)]     = __floats2half2_rn(v.x, v.y);
    o[2 * (base + i) + 1] = __floats2half2_rn(v.z, v.w);
    if (i < Ss) rowsum[b * Ss + i] = 0.0f;                  // zero this batch's row sums
}

// ---------------- host ----------------
extern "C" void kernel_launch(void* const* d_in, const int* in_sizes, int n_in,
                              void* d_out, int out_size)
{
    const float* x  = (const float*)d_in[0];
    const float* Wq = (const float*)d_in[1];
    const float* bq = (const float*)d_in[2];
    const float* Wk = (const float*)d_in[3];
    const float* bk = (const float*)d_in[4];
    const float* Wv = (const float*)d_in[5];
    const float* bv = (const float*)d_in[6];
    float* out = (float*)d_out;

    __half *x16, *W16, *Q16, *K16, *Vt16, *P16;
    float* rowsum;
    cudaGetSymbolAddress((void**)&x16, g_x16);
    cudaGetSymbolAddress((void**)&W16, g_W16);
    cudaGetSymbolAddress((void**)&Q16, g_Q16);
    cudaGetSymbolAddress((void**)&K16, g_K16);
    cudaGetSymbolAddress((void**)&Vt16, g_Vt16);
    cudaGetSymbolAddress((void**)&P16, g_P16);
    cudaGetSymbolAddress((void**)&rowsum, g_rowsum);

    cudaFuncSetAttribute((const void*)proj_b_kernel,
                         cudaFuncAttributeMaxDynamicSharedMemorySize, SMEM_BYTES);
    cudaFuncSetAttribute((const void*)scores_b_kernel,
                         cudaFuncAttributeMaxDynamicSharedMemorySize, SMEM_BYTES);
    cudaFuncSetAttribute((const void*)pv_b_kernel,
                         cudaFuncAttributeMaxDynamicSharedMemorySize, SMEM_BYTES);

    // One-time side-stream / event creation (host resources only, no device memory).
    static cudaStream_t st[3] = {nullptr, nullptr, nullptr};
    static cudaEvent_t eFork = nullptr;
    static cudaEvent_t eJoin[3] = {nullptr, nullptr, nullptr};
    if (st[0] == nullptr) {
        for (int i = 0; i < 3; i++) {
            cudaStreamCreateWithFlags(&st[i], cudaStreamNonBlocking);
            cudaEventCreateWithFlags(&eJoin[i], cudaEventDisableTiming);
        }
        cudaEventCreateWithFlags(&eFork, cudaEventDisableTiming);
    }

    const dim3 gS(Ss / BN, Ss / BM);   // 16x16 per batch
    const dim3 gP(Dd / BN, Ss / BM);   // 8x16 per batch

    // 0) shared prologue: weights only (the one dependency every chain shares)
    cvt_w_kernel<<<3072, 256>>>(Wq, Wk, Wv, W16);

    // fork: side streams depend only on the weight convert
    cudaEventRecord(eFork, 0);
    for (int i = 0; i < 3; i++) cudaStreamWaitEvent(st[i], eFork, 0);

    // Four independent batch chains, one per stream (batch 0 on the origin
    // stream). Each chain: cvt_x(b) -> proj(b) -> scores(b) -> pv(b).
    // Per-chain x conversion removes ~8us of full-x convert from the serial
    // head; the four slice-converts overlap with each other and with earlier
    // chains' GEMM work.
    for (int b = 0; b < Bb; b++) {
        cudaStream_t s = (b == 0) ? (cudaStream_t)0 : st[b - 1];
        cvt_x_b_kernel<<<2048, 256, 0, s>>>(b, x, x16, rowsum);
        proj_b_kernel<<<384, NT, SMEM_BYTES, s>>>(b, x16, W16, bq, bk, bv, Q16, K16, Vt16);
        scores_b_kernel<<<gS, NT, SMEM_BYTES, s>>>(b, Q16, K16, P16, rowsum);
        pv_b_kernel<<<gP, NT, SMEM_BYTES, s>>>(b, P16, Vt16, rowsum, out);
    }

    // join: origin stream waits for all side chains
    for (int i = 0; i < 3; i++) {
        cudaEventRecord(eJoin[i], st[i]);
        cudaStreamWaitEvent(0, eJoin[i], 0);
    }
}

// round 17
// speedup vs baseline: 1.2327x; 1.0002x over previous
#include <cuda_runtime.h>
#include <cuda_fp16.h>
#include <cstdint>

#define Bb 4
#define Ss 2048
#define Dd 1024

#define BM 128
#define BN 128
#define BK 64                                  // fp16: 64 * 2B = 128B per row
#define A_BYTES (BM * 128)                     // 16KB
#define STAGE_BYTES (2 * A_BYTES)              // 32KB
#define SMEM_BYTES (3 * STAGE_BYTES)           // 96KB, 3 stages (best measured config)
#define NT 128                                 // threads per GEMM CTA (4 warps, 2x2)

// ---------------- device scratch (allocation-free rule) ----------------
__device__ __align__(1024) __half g_x16[Bb * Ss * Dd];
__device__ __align__(1024) __half g_W16[3 * Dd * Dd];
__device__ __align__(1024) __half g_Q16[Bb * Ss * Dd];
__device__ __align__(1024) __half g_K16[Bb * Ss * Dd];
__device__ __align__(1024) __half g_Vt16[Bb * Ss * Dd];
__device__ __align__(1024) __half g_P16[Bb * Ss * Ss];
__device__ float g_rowsum[Bb * Ss];

// ---------------- helpers ----------------
__device__ __forceinline__ uint32_t smem_u32(const void* p) {
    uint32_t a;
    asm("{ .reg .u64 t; cvta.to.shared.u64 t, %1; cvt.u32.u64 %0, t; }" : "=r"(a) : "l"(p));
    return a;
}
__device__ __forceinline__ void cp16(uint32_t dst, const void* src) {
    asm volatile("cp.async.cg.shared.global [%0], [%1], 16;" :: "r"(dst), "l"(src));
}
__device__ __forceinline__ void cp_commit() {
    asm volatile("cp.async.commit_group;" ::: "memory");
}
__device__ __forceinline__ void cp_wait1() {
    asm volatile("cp.async.wait_group 1;" ::: "memory");
}
__device__ __forceinline__ void ldsm4(uint32_t& r0, uint32_t& r1, uint32_t& r2, uint32_t& r3,
                                      uint32_t addr) {
    asm volatile("ldmatrix.sync.aligned.m8n8.x4.shared.b16 {%0,%1,%2,%3}, [%4];"
                 : "=r"(r0), "=r"(r1), "=r"(r2), "=r"(r3) : "r"(addr));
}
__device__ __forceinline__ void mma_f16(float* c, const uint32_t* a, uint32_t b0, uint32_t b1) {
    asm volatile(
        "mma.sync.aligned.m16n8k16.row.col.f32.f16.f16.f32 "
        "{%0,%1,%2,%3}, {%4,%5,%6,%7}, {%8,%9}, {%0,%1,%2,%3};"
        : "+f"(c[0]), "+f"(c[1]), "+f"(c[2]), "+f"(c[3])
        : "r"(a[0]), "r"(a[1]), "r"(a[2]), "r"(a[3]), "r"(b0), "r"(b1));
}
// exp(v) * 2^-4 == exp2(v*log2e - 4): one FFMA + EX2 (folds the 2^-4 into the exponent)
__device__ __forceinline__ float exp_s4(float v) {
    return exp2f(fmaf(v, 1.44269504f, -4.0f));
}

// ======= fp16 mma.sync GEMM body (verbatim best-measured R11 config) =======
// 128 threads, 4 warps 2(M)x2(N), warp tile 64x64, 3-stage cp.async ring, 2 CTAs/SM.
// EPI: 1 = fp16 out, alpha + per-column bias
//      2 = fp16 out, alpha + per-row bias
//      3 = fp16 out, exp(alpha*s)*2^-4, fused row-sum atomicAdd into aux
//      4 = fp32 out, acc * (1/aux[row])          (PV normalize)
template <int EPI>
__device__ __forceinline__ void gemm_body(
    const __half* __restrict__ Ab, const __half* __restrict__ Bg0,
    const float* __restrict__ bias, float* __restrict__ aux,
    void* __restrict__ Cv, int Ntot, int Ktot, float alpha,
    int rowBase, int colBase, uint32_t sb)
{
    const int tid = threadIdx.x;
    const int lane = tid & 31;
    const int wid = tid >> 5;
    const int wm = wid & 1;        // 2 warps in M (64 rows each)
    const int wn = wid >> 1;       // 2 warps in N (64 cols each)

    const int lr = tid >> 3;       // 0..15
    const int lc = tid & 7;        // 0..7
    const uint32_t soff0 = lr * 128 + ((uint32_t)(lc ^ (lr & 7)) << 4);
    const int st16 = 16 * Ktot;
    const __half* pA = Ab + (long long)lr * Ktot + lc * 8;
    const __half* pB = Bg0 + (long long)lr * Ktot + lc * 8;

    const int frow = lane & 15;
    const int fkc = lane >> 4;

    float acc[4][8][4];
#pragma unroll
    for (int i = 0; i < 4; i++)
#pragma unroll
        for (int j = 0; j < 8; j++)
#pragma unroll
            for (int q = 0; q < 4; q++) acc[i][j][q] = 0.0f;

    const int kIters = Ktot / BK;

    auto load_stage = [&](int buf) {
        const uint32_t sbase = sb + buf * STAGE_BYTES + soff0;
#pragma unroll
        for (int p = 0; p < 8; p++) {
            cp16(sbase + p * 2048, pA + p * st16);
            cp16(sbase + A_BYTES + p * 2048, pB + p * st16);
        }
        pA += BK;
        pB += BK;
    };

    load_stage(0); cp_commit();
    load_stage(1); cp_commit();

    int arow[4], brow[4];
#pragma unroll
    for (int mt = 0; mt < 4; mt++) arow[mt] = wm * 64 + mt * 16 + frow;
#pragma unroll
    for (int p = 0; p < 4; p++) brow[p] = wn * 64 + p * 16 + frow;

    int nbuf = 2;
    int cbuf = 0;
    for (int it = 0; it < kIters; it++) {
        cp_wait1();
        __syncthreads();

        if (it + 2 < kIters) load_stage(nbuf);
        cp_commit();
        nbuf = (nbuf + 1 == 3) ? 0 : nbuf + 1;

        const uint32_t As = sb + cbuf * STAGE_BYTES;
        const uint32_t Bs = As + A_BYTES;
        cbuf = (cbuf + 1 == 3) ? 0 : cbuf + 1;

#pragma unroll
        for (int ks = 0; ks < 4; ks++) {
            const int chunk = 2 * ks + fkc;
            uint32_t a[4][4];
#pragma unroll
            for (int mt = 0; mt < 4; mt++) {
                const uint32_t ad = As + arow[mt] * 128 +
                                    ((uint32_t)(chunk ^ (arow[mt] & 7)) << 4);
                ldsm4(a[mt][0], a[mt][1], a[mt][2], a[mt][3], ad);
            }
            uint32_t b[4][4];
#pragma unroll
            for (int p = 0; p < 4; p++) {
                const uint32_t bd = Bs + brow[p] * 128 +
                                    ((uint32_t)(chunk ^ (brow[p] & 7)) << 4);
                ldsm4(b[p][0], b[p][1], b[p][2], b[p][3], bd);
            }
#pragma unroll
            for (int mt = 0; mt < 4; mt++)
#pragma unroll
                for (int nt = 0; nt < 8; nt++) {
                    const int p = nt >> 1, o = nt & 1;
                    mma_f16(acc[mt][nt], a[mt], b[p][o], b[p][2 + o]);
                }
        }
    }

    // ---- epilogue ----
    const int g = lane >> 2;
    const int cpair = (lane & 3) * 2;
#pragma unroll
    for (int mt = 0; mt < 4; mt++) {
        const long long r0 = rowBase + wm * 64 + mt * 16 + g;
        const long long r1 = r0 + 8;
        float rb0 = 0.f, rb1 = 0.f;
        if (EPI == 2) { rb0 = bias[r0]; rb1 = bias[r1]; }
        if (EPI == 4) { rb0 = 1.0f / aux[r0]; rb1 = 1.0f / aux[r1]; }
        float sum0 = 0.f, sum1 = 0.f;
#pragma unroll
        for (int nt = 0; nt < 8; nt++) {
            const int col = colBase + wn * 64 + nt * 8 + cpair;
            float v00 = acc[mt][nt][0] * alpha;
            float v01 = acc[mt][nt][1] * alpha;
            float v10 = acc[mt][nt][2] * alpha;
            float v11 = acc[mt][nt][3] * alpha;
            if (EPI == 1) {
                const float bx = bias[col], by = bias[col + 1];
                v00 += bx; v01 += by; v10 += bx; v11 += by;
            }
            if (EPI == 2) { v00 += rb0; v01 += rb0; v10 += rb1; v11 += rb1; }
            if (EPI == 3) {
                v00 = exp_s4(v00); v01 = exp_s4(v01);
                v10 = exp_s4(v10); v11 = exp_s4(v11);
                sum0 += v00 + v01; sum1 += v10 + v11;
            }
            if (EPI == 4) { v00 *= rb0; v01 *= rb0; v10 *= rb1; v11 *= rb1; }
            if (EPI == 4) {
                float* Cb = (float*)Cv;
                *reinterpret_cast<float2*>(Cb + r0 * Ntot + col) = make_float2(v00, v01);
                *reinterpret_cast<float2*>(Cb + r1 * Ntot + col) = make_float2(v10, v11);
            } else {
                __half* Cb = (__half*)Cv;
                *reinterpret_cast<__half2*>(Cb + r0 * Ntot + col) = __floats2half2_rn(v00, v01);
                *reinterpret_cast<__half2*>(Cb + r1 * Ntot + col) = __floats2half2_rn(v10, v11);
            }
        }
        if (EPI == 3) {
            sum0 += __shfl_xor_sync(0xFFFFFFFFu, sum0, 1);
            sum0 += __shfl_xor_sync(0xFFFFFFFFu, sum0, 2);
            sum1 += __shfl_xor_sync(0xFFFFFFFFu, sum1, 1);
            sum1 += __shfl_xor_sync(0xFFFFFFFFu, sum1, 2);
            if ((lane & 3) == 0) {
                atomicAdd(aux + r0, sum0);
                atomicAdd(aux + r1, sum1);
            }
        }
    }
}

// ======= per-batch QKV projection: 384 CTAs (QK 256 + Vt 128) =======
__global__ void __launch_bounds__(NT, 2) proj_b_kernel(
    int b,
    const __half* __restrict__ x16, const __half* __restrict__ W16,
    const float* __restrict__ bq, const float* __restrict__ bk, const float* __restrict__ bv,
    __half* __restrict__ Q16, __half* __restrict__ K16, __half* __restrict__ Vt16)
{
    extern __shared__ __align__(1024) char smem[];
    const uint32_t sb = smem_u32(smem);
    const long long SD = (long long)Ss * Dd;
    const long long DD = (long long)Dd * Dd;

    const int cta = blockIdx.x;
    if (cta < 256) {
        const int z = cta >> 7;
        const int rem = cta & 127;
        const int y = rem >> 3, x = rem & 7;
        const int rowBase = (b * 16 + y) * BM;
        gemm_body<1>(x16 + (long long)rowBase * Dd,
                     W16 + z * DD + (long long)x * BN * Dd,
                     z ? bk : bq, nullptr,
                     z ? K16 : Q16, Dd, Dd, 1.0f, rowBase, x * BN, sb);
    } else {
        const int i = cta - 256;
        const int y = i >> 4, x = i & 15;
        gemm_body<2>(W16 + 2 * DD + (long long)y * BM * Dd,
                     x16 + b * SD + (long long)x * BN * Dd,
                     bv, nullptr,
                     Vt16 + b * SD, Ss, Dd, 1.0f, y * BM, x * BN, sb);
    }
}

// ======= per-batch scores: P16 = exp(Q K^T / 32) * 2^-4, fused row sums =======
__global__ void __launch_bounds__(NT, 2) scores_b_kernel(
    int b,
    const __half* __restrict__ Q, const __half* __restrict__ K,
    __half* __restrict__ P, float* __restrict__ rowsum)
{
    extern __shared__ __align__(1024) char smem[];
    const uint32_t sb = smem_u32(smem);
    const long long SD = (long long)Ss * Dd;
    const long long SS2 = (long long)Ss * Ss;
    gemm_body<3>(Q + b * SD + (long long)blockIdx.y * BM * Dd,
                 K + b * SD + (long long)blockIdx.x * BN * Dd,
                 nullptr, rowsum + b * Ss,
                 P + b * SS2, Ss, Dd, 0.03125f,
                 blockIdx.y * BM, blockIdx.x * BN, sb);
}

// ======= per-batch PV: out = (P16 @ Vt^T) / rowsum[row] =======
__global__ void __launch_bounds__(NT, 2) pv_b_kernel(
    int b,
    const __half* __restrict__ P, const __half* __restrict__ Vt,
    const float* __restrict__ rowsum, float* __restrict__ out)
{
    extern __shared__ __align__(1024) char smem[];
    const uint32_t sb = smem_u32(smem);
    const long long SD = (long long)Ss * Dd;
    const long long SS2 = (long long)Ss * Ss;
    gemm_body<4>(P + b * SS2 + (long long)blockIdx.y * BM * Ss,
                 Vt + b * SD + (long long)blockIdx.x * BN * Ss,
                 nullptr, const_cast<float*>(rowsum) + b * Ss,
                 out + b * SD, Dd, Ss, 1.0f,
                 blockIdx.y * BM, blockIdx.x * BN, sb);
}

// ---------------- fp32 -> fp16 weight convert (3 weights, shared prologue) ----------------
__global__ void cvt_w_kernel(const float* __restrict__ wq, const float* __restrict__ wk,
                             const float* __restrict__ wv, __half* __restrict__ W16)
{
    const int wb = blockIdx.x;          // 0..3071
    const int w = wb >> 10;             // 0..2
    const float* src = (w == 0) ? wq : (w == 1) ? wk : wv;
    __half* dst = W16 + (long long)w * Dd * Dd;
    const int i = (wb & 1023) * 256 + threadIdx.x;
    const float4 v = reinterpret_cast<const float4*>(src)[i];
    __half2* o = reinterpret_cast<__half2*>(dst);
    o[2 * i]     = __floats2half2_rn(v.x, v.y);
    o[2 * i + 1] = __floats2half2_rn(v.z, v.w);
}

// ---------------- per-batch x-slice convert + rowsum zero (chain head) ----------------
__global__ void cvt_x_b_kernel(int b, const float* __restrict__ x,
                               __half* __restrict__ x16, float* __restrict__ rowsum)
{
    const long long base = (long long)b * (Ss * Dd / 4);   // float4 index base
    const int i = blockIdx.x * 256 + threadIdx.x;           // 0..524287
    const float4 v = reinterpret_cast<const float4*>(x)[base + i];
    __half2* o = reinterpret_cast<__half2*>(x16);
    o[2 * (base + i)]     = __floats2half2_rn(v.x, v.y);
    o[2 * (base + i) + 1] = __floats2half2_rn(v.z, v.w);
    if (i < Ss) rowsum[b * Ss + i] = 0.0f;                  // zero this batch's row sums
}

// ---------------- host ----------------
extern "C" void kernel_launch(void* const* d_in, const int* in_sizes, int n_in,
                              void* d_out, int out_size)
{
    const float* x  = (const float*)d_in[0];
    const float* Wq = (const float*)d_in[1];
    const float* bq = (const float*)d_in[2];
    const float* Wk = (const float*)d_in[3];
    const float* bk = (const float*)d_in[4];
    const float* Wv = (const float*)d_in[5];
    const float* bv = (const float*)d_in[6];
    float* out = (float*)d_out;

    __half *x16, *W16, *Q16, *K16, *Vt16, *P16;
    float* rowsum;
    cudaGetSymbolAddress((void**)&x16, g_x16);
    cudaGetSymbolAddress((void**)&W16, g_W16);
    cudaGetSymbolAddress((void**)&Q16, g_Q16);
    cudaGetSymbolAddress((void**)&K16, g_K16);
    cudaGetSymbolAddress((void**)&Vt16, g_Vt16);
    cudaGetSymbolAddress((void**)&P16, g_P16);
    cudaGetSymbolAddress((void**)&rowsum, g_rowsum);

    cudaFuncSetAttribute((const void*)proj_b_kernel,
                         cudaFuncAttributeMaxDynamicSharedMemorySize, SMEM_BYTES);
    cudaFuncSetAttribute((const void*)scores_b_kernel,
                         cudaFuncAttributeMaxDynamicSharedMemorySize, SMEM_BYTES);
    cudaFuncSetAttribute((const void*)pv_b_kernel,
                         cudaFuncAttributeMaxDynamicSharedMemorySize, SMEM_BYTES);

    // One-time side-stream / event creation (host resources only, no device memory).
    static cudaStream_t st[3] = {nullptr, nullptr, nullptr};
    static cudaEvent_t eStart = nullptr, eFork = nullptr;
    static cudaEvent_t eJoin[3] = {nullptr, nullptr, nullptr};
    if (st[0] == nullptr) {
        for (int i = 0; i < 3; i++) {
            cudaStreamCreateWithFlags(&st[i], cudaStreamNonBlocking);
            cudaEventCreateWithFlags(&eJoin[i], cudaEventDisableTiming);
        }
        cudaEventCreateWithFlags(&eStart, cudaEventDisableTiming);
        cudaEventCreateWithFlags(&eFork, cudaEventDisableTiming);
    }

    const dim3 gS(Ss / BN, Ss / BM);   // 16x16 per batch
    const dim3 gP(Dd / BN, Ss / BM);   // 8x16 per batch

    // Fork side streams at the very top: cvt_x(b) has NO dependency on cvt_w,
    // so side chains start their x-slice converts concurrently with the
    // weight convert on the origin stream.
    cudaEventRecord(eStart, 0);
    for (int i = 0; i < 3; i++) cudaStreamWaitEvent(st[i], eStart, 0);

    // origin: weight convert (the only shared dependency), then chain 0's cvt_x
    cvt_w_kernel<<<3072, 256>>>(Wq, Wk, Wv, W16);
    cudaEventRecord(eFork, 0);
    cvt_x_b_kernel<<<2048, 256>>>(0, x, x16, rowsum);

    // side streams: cvt_x immediately, then gate proj on the weight convert
    for (int i = 0; i < 3; i++) {
        cvt_x_b_kernel<<<2048, 256, 0, st[i]>>>(i + 1, x, x16, rowsum);
        cudaStreamWaitEvent(st[i], eFork, 0);
    }

    // Four independent batch chains: proj(b) -> scores(b) -> pv(b)
    for (int b = 0; b < Bb; b++) {
        cudaStream_t s = (b == 0) ? (cudaStream_t)0 : st[b - 1];
        proj_b_kernel<<<384, NT, SMEM_BYTES, s>>>(b, x16, W16, bq, bk, bv, Q16, K16, Vt16);
        scores_b_kernel<<<gS, NT, SMEM_BYTES, s>>>(b, Q16, K16, P16, rowsum);
        pv_b_kernel<<<gP, NT, SMEM_BYTES, s>>>(b, P16, Vt16, rowsum, out);
    }

    // join: origin stream waits for all side chains
    for (int i = 0; i < 3; i++) {
        cudaEventRecord(eJoin[i], st[i]);
        cudaStreamWaitEvent(0, eJoin[i], 0);
    }
}